// round 16
// baseline (speedup 1.0000x reference)
#include <cuda_runtime.h>
#include <cuda_bf16.h>
#include <cuda_fp16.h>
#include <math.h>
#include <stdint.h>

#define NN 50000
#define NE 100000
#define NB 2048
#define D  64

// ---------------- scratch (device globals; no allocation allowed) -------------
__device__ __align__(16) __nv_bfloat16 g_h1b[(size_t)NE * 128];
__device__ __align__(16) __nv_bfloat16 g_w2b[(size_t)4096 * 128];
__device__ __align__(16) __half g_ew[(size_t)NE * 4096];   // 0.82 GB fp16
__device__ float    g_out[NN * D];              // node state (h == out)
__device__ float    g_agg[NN * D];              // message accumulator
__device__ float    g_invdeg[NN];               // holds raw degree count
__device__ float    g_e[NN];
__device__ unsigned g_segmax[NB];
__device__ float    g_denom[NB];
__device__ float    g_r[NB * D];                // UNNORMALIZED attention readout
__device__ float    g_hh[NB * D];
__device__ float    g_cc[NB * D];

__device__ __forceinline__ float sigmoidf_(float x) { return 1.f / (1.f + expf(-x)); }

__device__ __forceinline__ unsigned fkey(float f) {
    unsigned b = __float_as_uint(f);
    return (b & 0x80000000u) ? ~b : (b | 0x80000000u);
}
__device__ __forceinline__ float fdec(unsigned k) {
    unsigned b = (k & 0x80000000u) ? (k ^ 0x80000000u) : ~k;
    return __uint_as_float(b);
}

// ---------------- mega-fused head ----------------
// block ranges (disjoint, no ordering needed):
//   [0, NE/2):            edge net layer 1 (2 edges/block) -> g_h1b
//   [NE/2, +2048):        w2 fp32 -> bf16
//   [.., +NN/4):          lin0 + relu -> g_out, zero g_agg
//   [.., +196):           zero invdeg / denom / segmax
#define HB_EDGE   (NE / 2)
#define HB_W2     (HB_EDGE + 2048)
#define HB_LIN0   (HB_W2 + NN / 4)
#define HB_ZERO   (HB_LIN0 + 196)
__global__ void k_head(const float* __restrict__ ea, const float* __restrict__ w1,
                       const float* __restrict__ b1, const float* __restrict__ w2,
                       const float* __restrict__ x, const float* __restrict__ l0w,
                       const float* __restrict__ l0b) {
    int blk = blockIdx.x;
    if (blk < HB_EDGE) {
        int k = threadIdx.x & 127;
        int e = blk * 2 + (threadIdx.x >> 7);
        float a0 = ea[e * 4 + 0], a1 = ea[e * 4 + 1], a2 = ea[e * 4 + 2], a3 = ea[e * 4 + 3];
        float acc = b1[k] + a0 * w1[k * 4 + 0] + a1 * w1[k * 4 + 1] +
                    a2 * w1[k * 4 + 2] + a3 * w1[k * 4 + 3];
        g_h1b[(size_t)e * 128 + k] = __float2bfloat16(fmaxf(acc, 0.f));
    } else if (blk < HB_W2) {
        int i = (blk - HB_EDGE) * 256 + threadIdx.x;  // covers 4096*128
        g_w2b[i] = __float2bfloat16(w2[i]);
    } else if (blk < HB_LIN0) {
        __shared__ float xs[4][14];
        int g = threadIdx.x >> 6, o = threadIdx.x & 63;
        int n = (blk - HB_W2) * 4 + g;
        if (o < 14) xs[g][o] = x[n * 14 + o];
        __syncthreads();
        float acc = l0b[o];
#pragma unroll
        for (int j = 0; j < 14; j++) acc += xs[g][j] * l0w[o * 14 + j];
        g_out[n * D + o] = fmaxf(acc, 0.f);
        g_agg[n * D + o] = 0.f;
    } else {
        int i = (blk - HB_LIN0) * 256 + threadIdx.x;
        if (i < NN) g_invdeg[i] = 0.f;
        if (i < NB) { g_denom[i] = 0.f; g_segmax[i] = 0u; }
    }
}

__global__ void k_zero_s2s() {
    int i = blockIdx.x * 256 + threadIdx.x;  // grid covers NB*192 exactly
    if (i < NB * 64) g_r[i] = 0.f;
    else if (i < NB * 128) g_hh[i - NB * 64] = 0.f;
    else g_cc[i - NB * 128] = 0.f;
}

// ---------------- HMMA / ldmatrix helpers ----------------
__device__ __forceinline__ void mma_bf16(float* c, const uint32_t* a,
                                         uint32_t b0, uint32_t b1) {
    asm volatile(
        "mma.sync.aligned.m16n8k16.row.col.f32.bf16.bf16.f32 "
        "{%0,%1,%2,%3}, {%4,%5,%6,%7}, {%8,%9}, {%0,%1,%2,%3};"
        : "+f"(c[0]), "+f"(c[1]), "+f"(c[2]), "+f"(c[3])
        : "r"(a[0]), "r"(a[1]), "r"(a[2]), "r"(a[3]), "r"(b0), "r"(b1));
}
__device__ __forceinline__ void ldm4(uint32_t* r, uint32_t addr) {
    asm volatile(
        "ldmatrix.sync.aligned.m8n8.x4.shared.b16 {%0,%1,%2,%3}, [%4];"
        : "=r"(r[0]), "=r"(r[1]), "=r"(r[2]), "=r"(r[3]) : "r"(addr));
}

// ---------------- big GEMM on HMMA: ew = h1 @ W2^T + b2 (fp16 out) ----------
#define LDW 68
#define LDC 68
__global__ void __launch_bounds__(128, 2)
k_gemm_hmma(const float* __restrict__ b2) {
    extern __shared__ uint32_t sw[];
    uint32_t* As = sw;                 // 128*LDW
    uint32_t* Bs = As + 128 * LDW;     // 128*LDW
    const int tid = threadIdx.x;
    const int m0 = blockIdx.y * 128, n0 = blockIdx.x * 128;

    {
        const int chunk = tid & 15;
        const int rsub  = tid >> 4;
        const char* srcA = (const char*)g_h1b;
        const char* srcB = (const char*)g_w2b;
#pragma unroll
        for (int p = 0; p < 16; p++) {
            int r = p * 8 + rsub;
            int m = m0 + r;
            uint4 va = (m < NE)
                ? *(const uint4*)(srcA + (size_t)m * 256 + chunk * 16)
                : make_uint4(0u, 0u, 0u, 0u);
            *(uint4*)(As + r * LDW + chunk * 4) = va;
            uint4 vb = *(const uint4*)(srcB + (size_t)(n0 + r) * 256 + chunk * 16);
            *(uint4*)(Bs + r * LDW + chunk * 4) = vb;
        }
    }
    __syncthreads();

    const int wid = tid >> 5, lane = tid & 31;
    const int warpM = wid >> 1, warpN = wid & 1;
    const int g = lane >> 2, tg = lane & 3;

    const uint32_t As_sh = (uint32_t)__cvta_generic_to_shared(As);
    const uint32_t Bs_sh = (uint32_t)__cvta_generic_to_shared(Bs);
    const uint32_t koff = (uint32_t)((lane >> 4) * 16);
    const uint32_t a_base = As_sh + (uint32_t)((warpM * 64 + (lane & 15)) * LDW) * 4 + koff;
    const uint32_t b_base = Bs_sh + (uint32_t)((warpN * 64 + (lane & 15)) * LDW) * 4 + koff;

    float c[4][8][4];
#pragma unroll
    for (int mi = 0; mi < 4; mi++)
#pragma unroll
        for (int ni = 0; ni < 8; ni++)
#pragma unroll
            for (int q = 0; q < 4; q++) c[mi][ni][q] = 0.f;

#pragma unroll
    for (int s = 0; s < 8; s++) {
        const uint32_t kbyte = (uint32_t)(s * 32);
        uint32_t a[4][4], b[4][4];
#pragma unroll
        for (int mi = 0; mi < 4; mi++)
            ldm4(a[mi], a_base + (uint32_t)(mi * 16 * LDW * 4) + kbyte);
#pragma unroll
        for (int np = 0; np < 4; np++)
            ldm4(b[np], b_base + (uint32_t)(np * 16 * LDW * 4) + kbyte);
#pragma unroll
        for (int np = 0; np < 4; np++) {
#pragma unroll
            for (int mi = 0; mi < 4; mi++) {
                mma_bf16(c[mi][2 * np],     a[mi], b[np][0], b[np][2]);
                mma_bf16(c[mi][2 * np + 1], a[mi], b[np][1], b[np][3]);
            }
        }
    }

    __syncthreads();
    {
        __half2* Cs = (__half2*)sw;
        const int colbase = n0 + warpN * 64 + 2 * tg;
        const int colh = warpN * 32 + tg;
        float2 bias[8];
#pragma unroll
        for (int ni = 0; ni < 8; ni++)
            bias[ni] = *(const float2*)(b2 + colbase + ni * 8);
#pragma unroll
        for (int mi = 0; mi < 4; mi++) {
            int r0 = warpM * 64 + mi * 16 + g;
            __half2* cp0 = Cs + r0 * LDC + colh;
            __half2* cp1 = Cs + (r0 + 8) * LDC + colh;
#pragma unroll
            for (int ni = 0; ni < 8; ni++) {
                cp0[ni * 4] = __floats2half2_rn(c[mi][ni][0] + bias[ni].x,
                                                c[mi][ni][1] + bias[ni].y);
                cp1[ni * 4] = __floats2half2_rn(c[mi][ni][2] + bias[ni].x,
                                                c[mi][ni][3] + bias[ni].y);
            }
        }
        __syncthreads();
        const int cseg = tid & 15;
        const int rbase = tid >> 4;
        const char* csrc = (const char*)Cs;
#pragma unroll
        for (int rr = 0; rr < 16; rr++) {
            int r = rr * 8 + rbase;
            int m = m0 + r;
            if (m < NE) {
                uint4 v = *(const uint4*)(csrc + (size_t)r * (LDC * 4) + cseg * 16);
                *(uint4*)((char*)(g_ew + (size_t)m * 4096 + n0) + cseg * 16) = v;
            }
        }
    }
}

// ---------------- per-edge matvec + scatter (one warp per edge, 16B loads) --
// docount != 0 on the first round: also count in-degrees (one atomic/edge).
__global__ void k_msg(const int* __restrict__ ei, int docount) {
    __shared__ float so[8][64];
    int g = threadIdx.x >> 5, lane = threadIdx.x & 31;
    int e = blockIdx.x * 8 + g;
    int s = ei[e], d = ei[NE + e];
    {
        float2 ov = *(const float2*)(g_out + s * D + lane * 2);
        so[g][lane * 2] = ov.x;
        so[g][lane * 2 + 1] = ov.y;
    }
    if (docount && lane == 0) atomicAdd(&g_invdeg[d], 1.f);
    __syncwarp();
    const char* base = (const char*)g_ew + (size_t)e * 8192;
    const int rsub = lane >> 3;
    const int csub = lane & 7;
    float acc[8];
#pragma unroll
    for (int q = 0; q < 8; q++) acc[q] = 0.f;
#pragma unroll 4
    for (int t = 0; t < 16; t++) {
        int i = t * 4 + rsub;
        uint4 v = __ldcs((const uint4*)(base + (size_t)i * 128 + csub * 16));
        float sv = so[g][i];
        float2 f0 = __half22float2(*(__half2*)&v.x);
        float2 f1 = __half22float2(*(__half2*)&v.y);
        float2 f2 = __half22float2(*(__half2*)&v.z);
        float2 f3 = __half22float2(*(__half2*)&v.w);
        acc[0] += sv * f0.x; acc[1] += sv * f0.y;
        acc[2] += sv * f1.x; acc[3] += sv * f1.y;
        acc[4] += sv * f2.x; acc[5] += sv * f2.y;
        acc[6] += sv * f3.x; acc[7] += sv * f3.y;
    }
#pragma unroll
    for (int q = 0; q < 8; q++) {
        acc[q] += __shfl_xor_sync(0xffffffffu, acc[q], 8);
        acc[q] += __shfl_xor_sync(0xffffffffu, acc[q], 16);
    }
    if (rsub == 0) {
        float* ap = g_agg + d * D + csub * 8;
#pragma unroll
        for (int q = 0; q < 8; q++) atomicAdd(ap + q, acc[q]);
    }
}

// ---------------- fused conv_root + GRU (4 nodes/thread, 16 nodes/iter) ----
// g_invdeg holds raw degree counts; reciprocal computed inline.
#define WST 68
__global__ void k_node(const float* __restrict__ root, const float* __restrict__ cbias,
                       const float* __restrict__ wih, const float* __restrict__ whh,
                       const float* __restrict__ bih, const float* __restrict__ bhh) {
    extern __shared__ float sm[];
    float* root_t = sm;                 // 64*WST (transposed: [o][i])
    float* wih_s  = sm + 64 * WST;      // 192*WST
    float* whh_s  = wih_s + 192 * WST;
    float* cb_s   = whh_s + 192 * WST;  // 64
    float* bih_s  = cb_s + 64;          // 192
    float* bhh_s  = bih_s + 192;        // 192
    float* orow   = bhh_s + 192;        // 16*64
    float* mrow   = orow + 1024;        // 16*64
    int tid = threadIdx.x;
    for (int i = tid; i < 4096; i += 256) {
        int rr = i >> 6, cc = i & 63;
        root_t[cc * WST + rr] = root[i];
    }
    for (int i = tid; i < 192 * 64; i += 256) {
        int rr = i >> 6, cc = i & 63;
        wih_s[rr * WST + cc] = wih[i];
        whh_s[rr * WST + cc] = whh[i];
    }
    if (tid < 64) cb_s[tid] = cbias[tid];
    if (tid < 192) { bih_s[tid] = bih[tid]; bhh_s[tid] = bhh[tid]; }
    __syncthreads();
    const int q = tid >> 6, o = tid & 63;
    const float* rt = root_t + o * WST;
    const float* w0 = wih_s + o * WST;
    const float* w1 = wih_s + (64 + o) * WST;
    const float* w2 = wih_s + (128 + o) * WST;
    const float* v0 = whh_s + o * WST;
    const float* v1 = whh_s + (64 + o) * WST;
    const float* v2 = whh_s + (128 + o) * WST;

    for (int base = blockIdx.x * 16; base < NN; base += gridDim.x * 16) {
        float h[4], m[4];
#pragma unroll
        for (int j = 0; j < 4; j++) {
            int n = base + j * 4 + q;
            h[j] = g_out[n * D + o];
            orow[(j * 4 + q) * 64 + o] = h[j];
            float iv = 1.f / fmaxf(g_invdeg[n], 1.f);
            m[j] = cb_s[o] + g_agg[n * D + o] * iv;
            g_agg[n * D + o] = 0.f;
        }
        __syncthreads();
#pragma unroll 4
        for (int i4 = 0; i4 < 64; i4 += 4) {
            float4 R = *(const float4*)(rt + i4);
#pragma unroll
            for (int j = 0; j < 4; j++) {
                float4 H = *(const float4*)(orow + (j * 4 + q) * 64 + i4);
                m[j] += H.x * R.x + H.y * R.y + H.z * R.z + H.w * R.w;
            }
        }
#pragma unroll
        for (int j = 0; j < 4; j++) {
            m[j] = fmaxf(m[j], 0.f);
            mrow[(j * 4 + q) * 64 + o] = m[j];
        }
        __syncthreads();
        float gi0[4], gi1[4], gi2[4], gh0[4], gh1[4], gh2[4];
#pragma unroll
        for (int j = 0; j < 4; j++) {
            gi0[j] = bih_s[o]; gi1[j] = bih_s[64 + o]; gi2[j] = bih_s[128 + o];
            gh0[j] = bhh_s[o]; gh1[j] = bhh_s[64 + o]; gh2[j] = bhh_s[128 + o];
        }
#pragma unroll 2
        for (int i4 = 0; i4 < 64; i4 += 4) {
            float4 W0 = *(const float4*)(w0 + i4);
            float4 W1 = *(const float4*)(w1 + i4);
            float4 W2 = *(const float4*)(w2 + i4);
            float4 V0 = *(const float4*)(v0 + i4);
            float4 V1 = *(const float4*)(v1 + i4);
            float4 V2 = *(const float4*)(v2 + i4);
#pragma unroll
            for (int j = 0; j < 4; j++) {
                float4 M = *(const float4*)(mrow + (j * 4 + q) * 64 + i4);
                float4 H = *(const float4*)(orow + (j * 4 + q) * 64 + i4);
                gi0[j] += M.x * W0.x + M.y * W0.y + M.z * W0.z + M.w * W0.w;
                gi1[j] += M.x * W1.x + M.y * W1.y + M.z * W1.z + M.w * W1.w;
                gi2[j] += M.x * W2.x + M.y * W2.y + M.z * W2.z + M.w * W2.w;
                gh0[j] += H.x * V0.x + H.y * V0.y + H.z * V0.z + H.w * V0.w;
                gh1[j] += H.x * V1.x + H.y * V1.y + H.z * V1.z + H.w * V1.w;
                gh2[j] += H.x * V2.x + H.y * V2.y + H.z * V2.z + H.w * V2.w;
            }
        }
#pragma unroll
        for (int j = 0; j < 4; j++) {
            float r  = sigmoidf_(gi0[j] + gh0[j]);
            float z  = sigmoidf_(gi1[j] + gh1[j]);
            float nn = tanhf(gi2[j] + r * gh2[j]);
            float hn = (1.f - z) * nn + z * h[j];
            int n = base + j * 4 + q;
            g_out[n * D + o] = hn;
        }
        __syncthreads();
    }
}

// ---------------- Set2Set LSTM cell (reads [hh, r/denom]; re-zeros att state)
__global__ void k_lstm(const float* __restrict__ wih, const float* __restrict__ whh,
                       const float* __restrict__ bih, const float* __restrict__ bhh) {
    extern __shared__ float sm[];
    float* wih_s = sm;                   // 256*129
    float* whh_s = wih_s + 256 * 129;    // 256*65
    float* qs    = whh_s + 256 * 65;     // 128
    float* hs    = qs + 128;             // 64
    float* gsh   = hs + 64;              // 256
    int tid = threadIdx.x;
    for (int i = tid; i < 256 * 128; i += 256) {
        int rr = i >> 7, cc = i & 127;
        wih_s[rr * 129 + cc] = wih[i];
    }
    for (int i = tid; i < 256 * 64; i += 256) {
        int rr = i >> 6, cc = i & 63;
        whh_s[rr * 65 + cc] = whh[i];
    }
    float bsum = bih[tid] + bhh[tid];
    __syncthreads();
    for (int it = 0; it < 8; it++) {
        int b = blockIdx.x + 256 * it;
        if (tid < 64) { qs[tid] = g_hh[b * 64 + tid]; hs[tid] = g_hh[b * 64 + tid]; }
        else if (tid < 128) {
            float rs = 1.f / (g_denom[b] + 1e-16f);
            qs[tid] = g_r[b * 64 + tid - 64] * rs;
        }
        __syncthreads();
        if (tid < 64) g_r[b * 64 + tid] = 0.f;
        else if (tid == 64) { g_denom[b] = 0.f; g_segmax[b] = 0u; }
        float acc = bsum;
        const float* wr = wih_s + tid * 129;
#pragma unroll 16
        for (int i = 0; i < 128; i++) acc += qs[i] * wr[i];
        const float* vr = whh_s + tid * 65;
#pragma unroll 16
        for (int i = 0; i < 64; i++) acc += hs[i] * vr[i];
        gsh[tid] = acc;
        __syncthreads();
        if (tid < 64) {
            float ii = gsh[tid], ff = gsh[64 + tid], gg = gsh[128 + tid], oo = gsh[192 + tid];
            float c  = sigmoidf_(ff) * g_cc[b * 64 + tid] + sigmoidf_(ii) * tanhf(gg);
            float h2 = sigmoidf_(oo) * tanhf(c);
            g_cc[b * 64 + tid] = c;
            g_hh[b * 64 + tid] = h2;
        }
        __syncthreads();
    }
}

// ---------------- attention ----------------
__global__ void k_att1(const int* __restrict__ batch) {
    int n = blockIdx.x * 8 + (threadIdx.x >> 5);
    int lane = threadIdx.x & 31;
    int b = batch[n];
    float v = g_out[n * D + lane] * g_hh[b * D + lane] +
              g_out[n * D + lane + 32] * g_hh[b * D + lane + 32];
#pragma unroll
    for (int off = 16; off; off >>= 1) v += __shfl_xor_sync(0xffffffffu, v, off);
    if (lane == 0) {
        g_e[n] = v;
        atomicMax(&g_segmax[b], fkey(v));
    }
}
__global__ void k_att2(const int* __restrict__ batch) {
    int g = threadIdx.x >> 6, o = threadIdx.x & 63;
    int n = blockIdx.x * 4 + g;
    int b = batch[n];
    float a = expf(g_e[n] - fdec(g_segmax[b]));
    if (o == 0) atomicAdd(&g_denom[b], a);
    atomicAdd(&g_r[b * D + o], a * g_out[n * D + o]);
}

// ---------------- output MLP (reads [hh, r/denom]) ----------------
__global__ void k_final(const float* __restrict__ l1w, const float* __restrict__ l1b,
                        const float* __restrict__ l2w, const float* __restrict__ l2b,
                        float* __restrict__ y) {
    __shared__ float qs[128];
    __shared__ float y1[64];
    int b = blockIdx.x, tid = threadIdx.x;
    if (tid < 64) qs[tid] = g_hh[b * 64 + tid];
    else {
        float rs = 1.f / (g_denom[b] + 1e-16f);
        qs[tid] = g_r[b * 64 + tid - 64] * rs;
    }
    __syncthreads();
    if (tid < 64) {
        float acc = l1b[tid];
        const float* wr = l1w + tid * 128;
#pragma unroll 16
        for (int i = 0; i < 128; i++) acc += qs[i] * wr[i];
        y1[tid] = fmaxf(acc, 0.f) * l2w[tid];
    }
    __syncthreads();
    if (tid < 32) {
        float v = y1[tid] + y1[tid + 32];
#pragma unroll
        for (int off = 16; off; off >>= 1) v += __shfl_xor_sync(0xffffffffu, v, off);
        if (tid == 0) y[b] = v + l2b[0];
    }
}

// ---------------- launcher ----------------
extern "C" void kernel_launch(void* const* d_in, const int* in_sizes, int n_in,
                              void* d_out, int out_size) {
    const float* x        = (const float*)d_in[0];
    const int*   ei       = (const int*)d_in[1];
    const float* ea       = (const float*)d_in[2];
    const int*   batch    = (const int*)d_in[3];
    const float* lin0_w   = (const float*)d_in[4];
    const float* lin0_b   = (const float*)d_in[5];
    const float* nn_w1    = (const float*)d_in[6];
    const float* nn_b1    = (const float*)d_in[7];
    const float* nn_w2    = (const float*)d_in[8];
    const float* nn_b2    = (const float*)d_in[9];
    const float* conv_root= (const float*)d_in[10];
    const float* conv_bias= (const float*)d_in[11];
    const float* gwih     = (const float*)d_in[12];
    const float* gwhh     = (const float*)d_in[13];
    const float* gbih     = (const float*)d_in[14];
    const float* gbhh     = (const float*)d_in[15];
    const float* swih     = (const float*)d_in[16];
    const float* swhh     = (const float*)d_in[17];
    const float* sbih     = (const float*)d_in[18];
    const float* sbhh     = (const float*)d_in[19];
    const float* l1w      = (const float*)d_in[20];
    const float* l1b      = (const float*)d_in[21];
    const float* l2w      = (const float*)d_in[22];
    const float* l2b      = (const float*)d_in[23];
    float* yout = (float*)d_out;

    const int SMEM_GEMM  = 2 * 128 * LDW * 4;                                      // 69632
    const int SMEM_NODE  = (64 * WST + 2 * 192 * WST + 64 + 192 + 192 + 2048) * 4; // 131840
    const int SMEM_LSTM  = (256 * 129 + 256 * 65 + 128 + 64 + 256) * 4;            // 200448
    cudaFuncSetAttribute(k_gemm_hmma, cudaFuncAttributeMaxDynamicSharedMemorySize, SMEM_GEMM);
    cudaFuncSetAttribute(k_node,  cudaFuncAttributeMaxDynamicSharedMemorySize, SMEM_NODE);
    cudaFuncSetAttribute(k_lstm,  cudaFuncAttributeMaxDynamicSharedMemorySize, SMEM_LSTM);

    // launch order: k_node is the 4th launch (profiled slot)
    k_head<<<HB_ZERO, 256>>>(ea, nn_w1, nn_b1, nn_w2, x, lin0_w, lin0_b);  // 1
    k_gemm_hmma<<<dim3(32, (NE + 127) / 128), 128, SMEM_GEMM>>>(nn_b2);    // 2
    k_msg<<<NE / 8, 256>>>(ei, 1);                                         // 3 (+degree count)
    k_node<<<625, 256, SMEM_NODE>>>(conv_root, conv_bias, gwih, gwhh, gbih, gbhh);  // 4 <- profiled
    for (int t = 1; t < 3; t++) {
        k_msg<<<NE / 8, 256>>>(ei, 0);
        k_node<<<625, 256, SMEM_NODE>>>(conv_root, conv_bias, gwih, gwhh, gbih, gbhh);
    }
    // Set2Set (lstm re-zeros r/denom/segmax per step; r is unnormalized)
    k_zero_s2s<<<NB * 192 / 256, 256>>>();
    for (int s = 0; s < 3; s++) {
        k_lstm<<<256, 256, SMEM_LSTM>>>(swih, swhh, sbih, sbhh);
        k_att1<<<NN / 8, 256>>>(batch);
        k_att2<<<NN / 4, 256>>>(batch);
    }
    // readout MLP
    k_final<<<NB, 128>>>(l1w, l1b, l2w, l2b, yout);
}

// round 17
// speedup vs baseline: 1.2235x; 1.2235x over previous
#include <cuda_runtime.h>
#include <cuda_bf16.h>
#include <cuda_fp16.h>
#include <math.h>
#include <stdint.h>

#define NN 50000
#define NE 100000
#define NB 2048
#define D  64

// ---------------- scratch (device globals; no allocation allowed) -------------
__device__ __align__(16) __nv_bfloat16 g_h1b[(size_t)NE * 128];
__device__ __align__(16) __nv_bfloat16 g_w2b[(size_t)4096 * 128];
__device__ __align__(16) __half g_ew[(size_t)NE * 4096];   // 0.82 GB fp16
__device__ float    g_out[NN * D];              // node state (h == out)
__device__ float    g_agg[NN * D];              // message accumulator
__device__ float    g_invdeg[NN];               // holds raw degree count
__device__ float    g_e[NN];
__device__ unsigned g_segmax[NB];
__device__ float    g_denom[NB];
__device__ float    g_r[NB * D];                // UNNORMALIZED attention readout
__device__ float    g_hh[NB * D];
__device__ float    g_cc[NB * D];

__device__ __forceinline__ float sigmoidf_(float x) { return 1.f / (1.f + expf(-x)); }

__device__ __forceinline__ unsigned fkey(float f) {
    unsigned b = __float_as_uint(f);
    return (b & 0x80000000u) ? ~b : (b | 0x80000000u);
}
__device__ __forceinline__ float fdec(unsigned k) {
    unsigned b = (k & 0x80000000u) ? (k ^ 0x80000000u) : ~k;
    return __uint_as_float(b);
}

// ---------------- mega-fused head ----------------
#define HB_EDGE   (NE / 2)
#define HB_W2     (HB_EDGE + 2048)
#define HB_LIN0   (HB_W2 + NN / 4)
#define HB_ZERO   (HB_LIN0 + 196)
__global__ void k_head(const float* __restrict__ ea, const float* __restrict__ w1,
                       const float* __restrict__ b1, const float* __restrict__ w2,
                       const float* __restrict__ x, const float* __restrict__ l0w,
                       const float* __restrict__ l0b) {
    int blk = blockIdx.x;
    if (blk < HB_EDGE) {
        int k = threadIdx.x & 127;
        int e = blk * 2 + (threadIdx.x >> 7);
        float a0 = ea[e * 4 + 0], a1 = ea[e * 4 + 1], a2 = ea[e * 4 + 2], a3 = ea[e * 4 + 3];
        float acc = b1[k] + a0 * w1[k * 4 + 0] + a1 * w1[k * 4 + 1] +
                    a2 * w1[k * 4 + 2] + a3 * w1[k * 4 + 3];
        g_h1b[(size_t)e * 128 + k] = __float2bfloat16(fmaxf(acc, 0.f));
    } else if (blk < HB_W2) {
        int i = (blk - HB_EDGE) * 256 + threadIdx.x;
        g_w2b[i] = __float2bfloat16(w2[i]);
    } else if (blk < HB_LIN0) {
        __shared__ float xs[4][14];
        int g = threadIdx.x >> 6, o = threadIdx.x & 63;
        int n = (blk - HB_W2) * 4 + g;
        if (o < 14) xs[g][o] = x[n * 14 + o];
        __syncthreads();
        float acc = l0b[o];
#pragma unroll
        for (int j = 0; j < 14; j++) acc += xs[g][j] * l0w[o * 14 + j];
        g_out[n * D + o] = fmaxf(acc, 0.f);
        g_agg[n * D + o] = 0.f;
    } else {
        int i = (blk - HB_LIN0) * 256 + threadIdx.x;
        if (i < NN) g_invdeg[i] = 0.f;
        if (i < NB) { g_denom[i] = 0.f; g_segmax[i] = 0u; }
    }
}

__global__ void k_zero_s2s() {
    int i = blockIdx.x * 256 + threadIdx.x;
    if (i < NB * 64) g_r[i] = 0.f;
    else if (i < NB * 128) g_hh[i - NB * 64] = 0.f;
    else g_cc[i - NB * 128] = 0.f;
}

// ---------------- HMMA / ldmatrix helpers ----------------
__device__ __forceinline__ void mma_bf16(float* c, const uint32_t* a,
                                         uint32_t b0, uint32_t b1) {
    asm volatile(
        "mma.sync.aligned.m16n8k16.row.col.f32.bf16.bf16.f32 "
        "{%0,%1,%2,%3}, {%4,%5,%6,%7}, {%8,%9}, {%0,%1,%2,%3};"
        : "+f"(c[0]), "+f"(c[1]), "+f"(c[2]), "+f"(c[3])
        : "r"(a[0]), "r"(a[1]), "r"(a[2]), "r"(a[3]), "r"(b0), "r"(b1));
}
__device__ __forceinline__ void ldm4(uint32_t* r, uint32_t addr) {
    asm volatile(
        "ldmatrix.sync.aligned.m8n8.x4.shared.b16 {%0,%1,%2,%3}, [%4];"
        : "=r"(r[0]), "=r"(r[1]), "=r"(r[2]), "=r"(r[3]) : "r"(addr));
}

// ---------------- big GEMM on HMMA: ew = h1 @ W2^T + b2 (fp16 out) ----------
#define LDW 68
#define LDC 68
__global__ void __launch_bounds__(128, 2)
k_gemm_hmma(const float* __restrict__ b2) {
    extern __shared__ uint32_t sw[];
    uint32_t* As = sw;
    uint32_t* Bs = As + 128 * LDW;
    const int tid = threadIdx.x;
    const int m0 = blockIdx.y * 128, n0 = blockIdx.x * 128;

    {
        const int chunk = tid & 15;
        const int rsub  = tid >> 4;
        const char* srcA = (const char*)g_h1b;
        const char* srcB = (const char*)g_w2b;
#pragma unroll
        for (int p = 0; p < 16; p++) {
            int r = p * 8 + rsub;
            int m = m0 + r;
            uint4 va = (m < NE)
                ? *(const uint4*)(srcA + (size_t)m * 256 + chunk * 16)
                : make_uint4(0u, 0u, 0u, 0u);
            *(uint4*)(As + r * LDW + chunk * 4) = va;
            uint4 vb = *(const uint4*)(srcB + (size_t)(n0 + r) * 256 + chunk * 16);
            *(uint4*)(Bs + r * LDW + chunk * 4) = vb;
        }
    }
    __syncthreads();

    const int wid = tid >> 5, lane = tid & 31;
    const int warpM = wid >> 1, warpN = wid & 1;
    const int g = lane >> 2, tg = lane & 3;

    const uint32_t As_sh = (uint32_t)__cvta_generic_to_shared(As);
    const uint32_t Bs_sh = (uint32_t)__cvta_generic_to_shared(Bs);
    const uint32_t koff = (uint32_t)((lane >> 4) * 16);
    const uint32_t a_base = As_sh + (uint32_t)((warpM * 64 + (lane & 15)) * LDW) * 4 + koff;
    const uint32_t b_base = Bs_sh + (uint32_t)((warpN * 64 + (lane & 15)) * LDW) * 4 + koff;

    float c[4][8][4];
#pragma unroll
    for (int mi = 0; mi < 4; mi++)
#pragma unroll
        for (int ni = 0; ni < 8; ni++)
#pragma unroll
            for (int q = 0; q < 4; q++) c[mi][ni][q] = 0.f;

#pragma unroll
    for (int s = 0; s < 8; s++) {
        const uint32_t kbyte = (uint32_t)(s * 32);
        uint32_t a[4][4], b[4][4];
#pragma unroll
        for (int mi = 0; mi < 4; mi++)
            ldm4(a[mi], a_base + (uint32_t)(mi * 16 * LDW * 4) + kbyte);
#pragma unroll
        for (int np = 0; np < 4; np++)
            ldm4(b[np], b_base + (uint32_t)(np * 16 * LDW * 4) + kbyte);
#pragma unroll
        for (int np = 0; np < 4; np++) {
#pragma unroll
            for (int mi = 0; mi < 4; mi++) {
                mma_bf16(c[mi][2 * np],     a[mi], b[np][0], b[np][2]);
                mma_bf16(c[mi][2 * np + 1], a[mi], b[np][1], b[np][3]);
            }
        }
    }

    __syncthreads();
    {
        __half2* Cs = (__half2*)sw;
        const int colbase = n0 + warpN * 64 + 2 * tg;
        const int colh = warpN * 32 + tg;
        float2 bias[8];
#pragma unroll
        for (int ni = 0; ni < 8; ni++)
            bias[ni] = *(const float2*)(b2 + colbase + ni * 8);
#pragma unroll
        for (int mi = 0; mi < 4; mi++) {
            int r0 = warpM * 64 + mi * 16 + g;
            __half2* cp0 = Cs + r0 * LDC + colh;
            __half2* cp1 = Cs + (r0 + 8) * LDC + colh;
#pragma unroll
            for (int ni = 0; ni < 8; ni++) {
                cp0[ni * 4] = __floats2half2_rn(c[mi][ni][0] + bias[ni].x,
                                                c[mi][ni][1] + bias[ni].y);
                cp1[ni * 4] = __floats2half2_rn(c[mi][ni][2] + bias[ni].x,
                                                c[mi][ni][3] + bias[ni].y);
            }
        }
        __syncthreads();
        const int cseg = tid & 15;
        const int rbase = tid >> 4;
        const char* csrc = (const char*)Cs;
#pragma unroll
        for (int rr = 0; rr < 16; rr++) {
            int r = rr * 8 + rbase;
            int m = m0 + r;
            if (m < NE) {
                uint4 v = *(const uint4*)(csrc + (size_t)r * (LDC * 4) + cseg * 16);
                *(uint4*)((char*)(g_ew + (size_t)m * 4096 + n0) + cseg * 16) = v;
            }
        }
    }
}

// ---------------- per-edge matvec + scatter (one warp per edge, 16B loads) --
__global__ void k_msg(const int* __restrict__ ei, int docount) {
    __shared__ float so[8][64];
    int g = threadIdx.x >> 5, lane = threadIdx.x & 31;
    int e = blockIdx.x * 8 + g;
    int s = ei[e], d = ei[NE + e];
    {
        float2 ov = *(const float2*)(g_out + s * D + lane * 2);
        so[g][lane * 2] = ov.x;
        so[g][lane * 2 + 1] = ov.y;
    }
    if (docount && lane == 0) atomicAdd(&g_invdeg[d], 1.f);
    __syncwarp();
    const char* base = (const char*)g_ew + (size_t)e * 8192;
    const int rsub = lane >> 3;
    const int csub = lane & 7;
    float acc[8];
#pragma unroll
    for (int q = 0; q < 8; q++) acc[q] = 0.f;
#pragma unroll 4
    for (int t = 0; t < 16; t++) {
        int i = t * 4 + rsub;
        uint4 v = __ldcs((const uint4*)(base + (size_t)i * 128 + csub * 16));
        float sv = so[g][i];
        float2 f0 = __half22float2(*(__half2*)&v.x);
        float2 f1 = __half22float2(*(__half2*)&v.y);
        float2 f2 = __half22float2(*(__half2*)&v.z);
        float2 f3 = __half22float2(*(__half2*)&v.w);
        acc[0] += sv * f0.x; acc[1] += sv * f0.y;
        acc[2] += sv * f1.x; acc[3] += sv * f1.y;
        acc[4] += sv * f2.x; acc[5] += sv * f2.y;
        acc[6] += sv * f3.x; acc[7] += sv * f3.y;
    }
#pragma unroll
    for (int q = 0; q < 8; q++) {
        acc[q] += __shfl_xor_sync(0xffffffffu, acc[q], 8);
        acc[q] += __shfl_xor_sync(0xffffffffu, acc[q], 16);
    }
    if (rsub == 0) {
        float* ap = g_agg + d * D + csub * 8;
#pragma unroll
        for (int q = 0; q < 8; q++) atomicAdd(ap + q, acc[q]);
    }
}

// ---------------- fused conv_root + GRU (fp16 weights in SMEM, 3 blocks/SM) -
// 4 nodes/thread, 16 nodes/iter; grid 444 (=148*3), 50000 = 16*3125 exact.
#define WH 72   // half stride: 144B rows (16B-aligned), conflict-free phases
__device__ __forceinline__ float2 h2f(const uint4& v, int p) {
    return __half22float2(((const __half2*)&v)[p]);
}
__global__ void __launch_bounds__(256, 3)
k_node(const float* __restrict__ root, const float* __restrict__ cbias,
       const float* __restrict__ wih, const float* __restrict__ whh,
       const float* __restrict__ bih, const float* __restrict__ bhh) {
    extern __shared__ char smc[];
    __half* root_h = (__half*)smc;             // 64*WH  (transposed [o][i])
    __half* wih_h  = root_h + 64 * WH;         // 192*WH
    __half* whh_h  = wih_h + 192 * WH;         // 192*WH
    float*  cb_s   = (float*)(whh_h + 192 * WH);  // 64
    float*  bih_s  = cb_s + 64;                // 192
    float*  bhh_s  = bih_s + 192;              // 192
    float*  ivs    = bhh_s + 192;              // 16
    float*  orow   = ivs + 16;                 // 1024
    float*  mrow   = orow + 1024;              // 1024
    int tid = threadIdx.x;
    for (int i = tid; i < 4096; i += 256) {
        int rr = i >> 6, cc = i & 63;
        root_h[cc * WH + rr] = __float2half(root[i]);
    }
    for (int i = tid; i < 192 * 64; i += 256) {
        int rr = i >> 6, cc = i & 63;
        wih_h[rr * WH + cc] = __float2half(wih[i]);
        whh_h[rr * WH + cc] = __float2half(whh[i]);
    }
    if (tid < 64) cb_s[tid] = cbias[tid];
    if (tid < 192) { bih_s[tid] = bih[tid]; bhh_s[tid] = bhh[tid]; }
    __syncthreads();
    const int q = tid >> 6, o = tid & 63;
    const __half* rt = root_h + o * WH;
    const __half* w0 = wih_h + o * WH;
    const __half* w1 = wih_h + (64 + o) * WH;
    const __half* w2 = wih_h + (128 + o) * WH;
    const __half* v0 = whh_h + o * WH;
    const __half* v1 = whh_h + (64 + o) * WH;
    const __half* v2 = whh_h + (128 + o) * WH;

    for (int base = blockIdx.x * 16; base < NN; base += gridDim.x * 16) {
        float h[4], aj[4];
#pragma unroll
        for (int j = 0; j < 4; j++) {
            int n = base + j * 4 + q;
            h[j] = g_out[n * D + o];
            orow[(j * 4 + q) * 64 + o] = h[j];
            aj[j] = g_agg[n * D + o];
            g_agg[n * D + o] = 0.f;
        }
        if (o == 0) {
#pragma unroll
            for (int j = 0; j < 4; j++)
                ivs[j * 4 + q] = 1.f / fmaxf(g_invdeg[base + j * 4 + q], 1.f);
        }
        __syncthreads();
        float m[4];
#pragma unroll
        for (int j = 0; j < 4; j++) m[j] = cb_s[o] + aj[j] * ivs[j * 4 + q];
        // conv_root matvec
#pragma unroll 2
        for (int i8 = 0; i8 < 64; i8 += 8) {
            uint4 Rv = *(const uint4*)(rt + i8);
#pragma unroll
            for (int p = 0; p < 4; p++) {
                float2 rp = h2f(Rv, p);
#pragma unroll
                for (int j = 0; j < 4; j++) {
                    float2 Hp = *(const float2*)(orow + (j * 4 + q) * 64 + i8 + 2 * p);
                    m[j] += Hp.x * rp.x + Hp.y * rp.y;
                }
            }
        }
#pragma unroll
        for (int j = 0; j < 4; j++) {
            m[j] = fmaxf(m[j], 0.f);
            mrow[(j * 4 + q) * 64 + o] = m[j];
        }
        __syncthreads();
        float gi0[4], gi1[4], gi2[4], gh0[4], gh1[4], gh2[4];
#pragma unroll
        for (int j = 0; j < 4; j++) {
            gi0[j] = bih_s[o]; gi1[j] = bih_s[64 + o]; gi2[j] = bih_s[128 + o];
            gh0[j] = bhh_s[o]; gh1[j] = bhh_s[64 + o]; gh2[j] = bhh_s[128 + o];
        }
        for (int i8 = 0; i8 < 64; i8 += 8) {
            uint4 W0v = *(const uint4*)(w0 + i8);
            uint4 W1v = *(const uint4*)(w1 + i8);
            uint4 W2v = *(const uint4*)(w2 + i8);
            uint4 V0v = *(const uint4*)(v0 + i8);
            uint4 V1v = *(const uint4*)(v1 + i8);
            uint4 V2v = *(const uint4*)(v2 + i8);
#pragma unroll
            for (int p = 0; p < 4; p++) {
                float2 a0 = h2f(W0v, p), a1 = h2f(W1v, p), a2 = h2f(W2v, p);
                float2 b0 = h2f(V0v, p), b1 = h2f(V1v, p), b2 = h2f(V2v, p);
#pragma unroll
                for (int j = 0; j < 4; j++) {
                    float2 Mp = *(const float2*)(mrow + (j * 4 + q) * 64 + i8 + 2 * p);
                    float2 Hp = *(const float2*)(orow + (j * 4 + q) * 64 + i8 + 2 * p);
                    gi0[j] += Mp.x * a0.x + Mp.y * a0.y;
                    gi1[j] += Mp.x * a1.x + Mp.y * a1.y;
                    gi2[j] += Mp.x * a2.x + Mp.y * a2.y;
                    gh0[j] += Hp.x * b0.x + Hp.y * b0.y;
                    gh1[j] += Hp.x * b1.x + Hp.y * b1.y;
                    gh2[j] += Hp.x * b2.x + Hp.y * b2.y;
                }
            }
        }
#pragma unroll
        for (int j = 0; j < 4; j++) {
            float r  = sigmoidf_(gi0[j] + gh0[j]);
            float z  = sigmoidf_(gi1[j] + gh1[j]);
            float nn = tanhf(gi2[j] + r * gh2[j]);
            float hn = (1.f - z) * nn + z * h[j];
            int n = base + j * 4 + q;
            g_out[n * D + o] = hn;
        }
        __syncthreads();
    }
}

// ---------------- Set2Set LSTM cell (reads [hh, r/denom]; re-zeros att state)
__global__ void k_lstm(const float* __restrict__ wih, const float* __restrict__ whh,
                       const float* __restrict__ bih, const float* __restrict__ bhh) {
    extern __shared__ float sm[];
    float* wih_s = sm;                   // 256*129
    float* whh_s = wih_s + 256 * 129;    // 256*65
    float* qs    = whh_s + 256 * 65;     // 128
    float* hs    = qs + 128;             // 64
    float* gsh   = hs + 64;              // 256
    int tid = threadIdx.x;
    for (int i = tid; i < 256 * 128; i += 256) {
        int rr = i >> 7, cc = i & 127;
        wih_s[rr * 129 + cc] = wih[i];
    }
    for (int i = tid; i < 256 * 64; i += 256) {
        int rr = i >> 6, cc = i & 63;
        whh_s[rr * 65 + cc] = whh[i];
    }
    float bsum = bih[tid] + bhh[tid];
    __syncthreads();
    for (int it = 0; it < 8; it++) {
        int b = blockIdx.x + 256 * it;
        if (tid < 64) { qs[tid] = g_hh[b * 64 + tid]; hs[tid] = g_hh[b * 64 + tid]; }
        else if (tid < 128) {
            float rs = 1.f / (g_denom[b] + 1e-16f);
            qs[tid] = g_r[b * 64 + tid - 64] * rs;
        }
        __syncthreads();
        if (tid < 64) g_r[b * 64 + tid] = 0.f;
        else if (tid == 64) { g_denom[b] = 0.f; g_segmax[b] = 0u; }
        float acc = bsum;
        const float* wr = wih_s + tid * 129;
#pragma unroll 16
        for (int i = 0; i < 128; i++) acc += qs[i] * wr[i];
        const float* vr = whh_s + tid * 65;
#pragma unroll 16
        for (int i = 0; i < 64; i++) acc += hs[i] * vr[i];
        gsh[tid] = acc;
        __syncthreads();
        if (tid < 64) {
            float ii = gsh[tid], ff = gsh[64 + tid], gg = gsh[128 + tid], oo = gsh[192 + tid];
            float c  = sigmoidf_(ff) * g_cc[b * 64 + tid] + sigmoidf_(ii) * tanhf(gg);
            float h2 = sigmoidf_(oo) * tanhf(c);
            g_cc[b * 64 + tid] = c;
            g_hh[b * 64 + tid] = h2;
        }
        __syncthreads();
    }
}

// ---------------- attention ----------------
__global__ void k_att1(const int* __restrict__ batch) {
    int n = blockIdx.x * 8 + (threadIdx.x >> 5);
    int lane = threadIdx.x & 31;
    int b = batch[n];
    float v = g_out[n * D + lane] * g_hh[b * D + lane] +
              g_out[n * D + lane + 32] * g_hh[b * D + lane + 32];
#pragma unroll
    for (int off = 16; off; off >>= 1) v += __shfl_xor_sync(0xffffffffu, v, off);
    if (lane == 0) {
        g_e[n] = v;
        atomicMax(&g_segmax[b], fkey(v));
    }
}
__global__ void k_att2(const int* __restrict__ batch) {
    int g = threadIdx.x >> 6, o = threadIdx.x & 63;
    int n = blockIdx.x * 4 + g;
    int b = batch[n];
    float a = expf(g_e[n] - fdec(g_segmax[b]));
    if (o == 0) atomicAdd(&g_denom[b], a);
    atomicAdd(&g_r[b * D + o], a * g_out[n * D + o]);
}

// ---------------- output MLP (reads [hh, r/denom]) ----------------
__global__ void k_final(const float* __restrict__ l1w, const float* __restrict__ l1b,
                        const float* __restrict__ l2w, const float* __restrict__ l2b,
                        float* __restrict__ y) {
    __shared__ float qs[128];
    __shared__ float y1[64];
    int b = blockIdx.x, tid = threadIdx.x;
    if (tid < 64) qs[tid] = g_hh[b * 64 + tid];
    else {
        float rs = 1.f / (g_denom[b] + 1e-16f);
        qs[tid] = g_r[b * 64 + tid - 64] * rs;
    }
    __syncthreads();
    if (tid < 64) {
        float acc = l1b[tid];
        const float* wr = l1w + tid * 128;
#pragma unroll 16
        for (int i = 0; i < 128; i++) acc += qs[i] * wr[i];
        y1[tid] = fmaxf(acc, 0.f) * l2w[tid];
    }
    __syncthreads();
    if (tid < 32) {
        float v = y1[tid] + y1[tid + 32];
#pragma unroll
        for (int off = 16; off; off >>= 1) v += __shfl_xor_sync(0xffffffffu, v, off);
        if (tid == 0) y[b] = v + l2b[0];
    }
}

// ---------------- launcher ----------------
extern "C" void kernel_launch(void* const* d_in, const int* in_sizes, int n_in,
                              void* d_out, int out_size) {
    const float* x        = (const float*)d_in[0];
    const int*   ei       = (const int*)d_in[1];
    const float* ea       = (const float*)d_in[2];
    const int*   batch    = (const int*)d_in[3];
    const float* lin0_w   = (const float*)d_in[4];
    const float* lin0_b   = (const float*)d_in[5];
    const float* nn_w1    = (const float*)d_in[6];
    const float* nn_b1    = (const float*)d_in[7];
    const float* nn_w2    = (const float*)d_in[8];
    const float* nn_b2    = (const float*)d_in[9];
    const float* conv_root= (const float*)d_in[10];
    const float* conv_bias= (const float*)d_in[11];
    const float* gwih     = (const float*)d_in[12];
    const float* gwhh     = (const float*)d_in[13];
    const float* gbih     = (const float*)d_in[14];
    const float* gbhh     = (const float*)d_in[15];
    const float* swih     = (const float*)d_in[16];
    const float* swhh     = (const float*)d_in[17];
    const float* sbih     = (const float*)d_in[18];
    const float* sbhh     = (const float*)d_in[19];
    const float* l1w      = (const float*)d_in[20];
    const float* l1b      = (const float*)d_in[21];
    const float* l2w      = (const float*)d_in[22];
    const float* l2b      = (const float*)d_in[23];
    float* yout = (float*)d_out;

    const int SMEM_GEMM  = 2 * 128 * LDW * 4;                                     // 69632
    const int SMEM_NODE  = (64 + 192 + 192) * WH * 2 + (64 + 192 + 192 + 16 + 2048) * 4; // 74560
    const int SMEM_LSTM  = (256 * 129 + 256 * 65 + 128 + 64 + 256) * 4;           // 200448
    cudaFuncSetAttribute(k_gemm_hmma, cudaFuncAttributeMaxDynamicSharedMemorySize, SMEM_GEMM);
    cudaFuncSetAttribute(k_node,  cudaFuncAttributeMaxDynamicSharedMemorySize, SMEM_NODE);
    cudaFuncSetAttribute(k_lstm,  cudaFuncAttributeMaxDynamicSharedMemorySize, SMEM_LSTM);

    // launch order: k_node is the 4th launch (profiled slot)
    k_head<<<HB_ZERO, 256>>>(ea, nn_w1, nn_b1, nn_w2, x, lin0_w, lin0_b);  // 1
    k_gemm_hmma<<<dim3(32, (NE + 127) / 128), 128, SMEM_GEMM>>>(nn_b2);    // 2
    k_msg<<<NE / 8, 256>>>(ei, 1);                                         // 3 (+degree count)
    k_node<<<444, 256, SMEM_NODE>>>(conv_root, conv_bias, gwih, gwhh, gbih, gbhh);  // 4 <- profiled
    for (int t = 1; t < 3; t++) {
        k_msg<<<NE / 8, 256>>>(ei, 0);
        k_node<<<444, 256, SMEM_NODE>>>(conv_root, conv_bias, gwih, gwhh, gbih, gbhh);
    }
    // Set2Set (lstm re-zeros r/denom/segmax per step; r is unnormalized)
    k_zero_s2s<<<NB * 192 / 256, 256>>>();
    for (int s = 0; s < 3; s++) {
        k_lstm<<<256, 256, SMEM_LSTM>>>(swih, swhh, sbih, sbhh);
        k_att1<<<NN / 8, 256>>>(batch);
        k_att2<<<NN / 4, 256>>>(batch);
    }
    // readout MLP
    k_final<<<NB, 128>>>(l1w, l1b, l2w, l2b, yout);
}